// round 14
// baseline (speedup 1.0000x reference)
#include <cuda_runtime.h>
#include <cstdint>
#include <cstddef>

// ---------------------------------------------------------------------------
// GAT, N=6144, F_in=256, F_hid=64, F_out=32, H=4, dense adj.
// attn_ij = w_ij / sum_j w_ij with
//   w_ij = mask_ij * ( s2_j >= -s1_i ?  e^{s2_j} * e^{0.8 s1_i}  :  e^{0.2 s2_j} )
// Masked attention via warp-level tf32 HMMA (m16n8k8). This round:
// M_warp = 32 (2 m-tiles/warp) halves per-row B smem traffic (L1 was 75%);
// 128-thread CTAs, 4 CTA/SM; B fragments transient in registers.
// ---------------------------------------------------------------------------

typedef uint32_t u32;

constexpr int N_  = 6144;
constexpr int NH_ = 4;
constexpr int F1_ = 64;
constexpr int F2_ = 32;
constexpr int MW_ = N_ / 32;   // 192 mask words per row
constexpr int JS1_ = 3;        // j-splits, layer 1 -> 576 CTAs
constexpr int JS2_ = 12;       // j-splits, layer 2 -> 576 CTAs

struct Scratch {
    u32 mask[(size_t)N_ * MW_];
    float H1[(size_t)NH_ * N_ * F1_];
    float P1n[(size_t)JS1_ * NH_ * N_ * F1_];
    float P1d[(size_t)JS1_ * NH_ * N_];
    float x2[(size_t)N_ * F1_];
    float H2[(size_t)N_ * F2_];
    float P2n[(size_t)JS2_ * N_ * F2_];
    float P2d[(size_t)JS2_ * N_];
    float T1[NH_ * N_], R1[NH_ * N_], S21[NH_ * N_], E2p1[NH_ * N_], E2n1[NH_ * N_];
    float T2[N_], R2[N_], S22[N_], E2p2[N_], E2n2[N_];
};
__device__ Scratch g_s;

// ---------------- helpers ---------------------------------------------------
__device__ __forceinline__ u32 f2tf32(float x) {
    u32 r;
    asm("cvt.rna.tf32.f32 %0, %1;" : "=r"(r) : "f"(x));
    return r;
}
__device__ __forceinline__ void mma_tf32(float* c,
                                         u32 a0, u32 a1, u32 a2, u32 a3,
                                         u32 b0, u32 b1) {
    asm volatile(
        "mma.sync.aligned.m16n8k8.row.col.f32.tf32.tf32.f32 "
        "{%0,%1,%2,%3}, {%4,%5,%6,%7}, {%8,%9}, {%0,%1,%2,%3};"
        : "+f"(c[0]), "+f"(c[1]), "+f"(c[2]), "+f"(c[3])
        : "r"(a0), "r"(a1), "r"(a2), "r"(a3), "r"(b0), "r"(b1));
}

// ---------------- adj -> bitmask -------------------------------------------
__global__ void pack_kernel(const int* __restrict__ adj, u32* __restrict__ mb) {
    size_t gid = (size_t)blockIdx.x * blockDim.x + threadIdx.x;
    int v = adj[gid] > 0;
    u32 m = __ballot_sync(0xffffffffu, v);
    if ((threadIdx.x & 31) == 0) mb[gid >> 5] = m;
}

// ---------------- small fp32 GEMM: C[h] = A @ B[h], 8x4 per-thread ---------
template <int F>
__global__ void gemm_kernel(const float* __restrict__ A, const float* __restrict__ B,
                            float* __restrict__ C, int K) {
    constexpr int TX = F / 4;
    constexpr int TY = 256 / TX;
    constexpr int RM = TY * 8;
    constexpr int TK = 16;
    __shared__ float xs[RM][TK + 1];
    __shared__ float ws[TK][F + 4];
    const int h  = blockIdx.y;
    const int i0 = blockIdx.x * RM;
    const float* Bh = B + (size_t)h * K * F;
    float*       Ch = C + (size_t)h * N_ * F;
    const int tid = threadIdx.x;
    const int tx = tid % TX, ty = tid / TX;
    float acc[8][4] = {};
    for (int k0 = 0; k0 < K; k0 += TK) {
        for (int idx = tid; idx < RM * TK; idx += 256) {
            int r = idx / TK, c = idx % TK;
            xs[r][c] = A[(size_t)(i0 + r) * K + k0 + c];
        }
        for (int idx = tid; idx < TK * F; idx += 256) {
            int r = idx / F, c = idx % F;
            ws[r][c] = Bh[(size_t)(k0 + r) * F + c];
        }
        __syncthreads();
#pragma unroll
        for (int kk = 0; kk < TK; kk++) {
            float a[8], b[4];
#pragma unroll
            for (int r = 0; r < 8; r++) a[r] = xs[ty * 8 + r][kk];
#pragma unroll
            for (int c = 0; c < 4; c++) b[c] = ws[kk][tx * 4 + c];
#pragma unroll
            for (int r = 0; r < 8; r++)
#pragma unroll
                for (int c = 0; c < 4; c++)
                    acc[r][c] = fmaf(a[r], b[c], acc[r][c]);
        }
        __syncthreads();
    }
#pragma unroll
    for (int r = 0; r < 8; r++)
#pragma unroll
        for (int c = 0; c < 4; c++)
            Ch[(size_t)(i0 + ty * 8 + r) * F + tx * 4 + c] = acc[r][c];
}

// ---------------- per-node scores + precomputed exponentials ---------------
template <int F>
__global__ void scores_kernel(const float* __restrict__ H, const float* __restrict__ a,
                              float* __restrict__ T, float* __restrict__ R,
                              float* __restrict__ S2, float* __restrict__ E2p,
                              float* __restrict__ E2n, int NH) {
    int gw   = (int)((blockIdx.x * blockDim.x + threadIdx.x) >> 5);
    int lane = threadIdx.x & 31;
    if (gw >= NH * N_) return;
    int h = gw / N_, i = gw % N_;
    const float* Hi = H + ((size_t)h * N_ + i) * F;
    const float* a1 = a + (size_t)h * 2 * F;
    const float* a2 = a1 + F;
    float s1 = 0.f, s2 = 0.f;
    for (int f = lane; f < F; f += 32) {
        float hv = Hi[f];
        s1 = fmaf(hv, a1[f], s1);
        s2 = fmaf(hv, a2[f], s2);
    }
#pragma unroll
    for (int o = 16; o; o >>= 1) {
        s1 += __shfl_xor_sync(0xffffffffu, s1, o);
        s2 += __shfl_xor_sync(0xffffffffu, s2, o);
    }
    if (lane == 0) {
        int idx = h * N_ + i;
        T[idx]   = -s1;
        R[idx]   = expf(0.8f * s1);
        S2[idx]  = s2;
        E2p[idx] = expf(s2);
        E2n[idx] = expf(0.2f * s2);
    }
}

// ================== tf32 HMMA masked attention =============================
// 128 threads, 4 warps; warp owns 32 i-rows (2 m-tiles) x full F.
// A fragments (w) generated in registers; B = H tile staged in smem as tf32;
// each B-fragment LDS feeds 2 HMMAs. Raw numerator/denominator partials out.
template <int F>
__global__ void __launch_bounds__(128, 4)
attn_hmma_kernel(const float* __restrict__ H, const float* __restrict__ T,
                 const float* __restrict__ R, const float* __restrict__ S2,
                 const float* __restrict__ E2p, const float* __restrict__ E2n,
                 const u32* __restrict__ mask,
                 float* __restrict__ Pn, float* __restrict__ Pd, int jsCount) {
    constexpr int SB = F + 8;          // Bs row stride (conflict-free pattern)
    constexpr int NT = F / 8;          // n-tiles per warp
    constexpr int QT = F / 16;         // staging float4s per thread (128 thr)

    __shared__ u32  Bs[2][32 * SB];
    __shared__ float sSc[2][96];       // [s2 | e2p | e2n] x 32

    const int tid  = threadIdx.x;
    const int warp = tid >> 5;
    const int lane = tid & 31;
    const int grp  = lane >> 2;
    const int tg   = lane & 3;

    const int h   = blockIdx.y;
    const int js  = blockIdx.z;
    const int i0  = blockIdx.x * 128;
    const int jLen  = N_ / jsCount;
    const int jBase = js * jLen;
    const int nTiles = jLen / 32;

    const float* Hh  = H   + (size_t)h * N_ * F;
    const float* Th  = T   + (size_t)h * N_;
    const float* Rh  = R   + (size_t)h * N_;
    const float* S2h = S2  + (size_t)h * N_;
    const float* Pph = E2p + (size_t)h * N_;
    const float* Pnh = E2n + (size_t)h * N_;

    // 4 rows per thread: m-tile 0 -> row[0],row[1]; m-tile 1 -> row[2],row[3]
    int row[4];
    float Tr[4], Rr[4];
#pragma unroll
    for (int r = 0; r < 4; r++) {
        row[r] = i0 + warp * 32 + grp + 8 * r;
        Tr[r] = Th[row[r]];
        Rr[r] = Rh[row[r]];
    }

    float acc[2][NT][4];
#pragma unroll
    for (int m = 0; m < 2; m++)
#pragma unroll
        for (int nt = 0; nt < NT; nt++)
#pragma unroll
            for (int q = 0; q < 4; q++) acc[m][nt][q] = 0.f;
    float ds[4] = {0.f, 0.f, 0.f, 0.f};

    for (int t = 0; t < nTiles; t++) {
        const int buf = t & 1;
        const int jA  = jBase + t * 32;

        // mask words for this thread's 4 rows (issued before the barrier)
        u32 mw[4];
#pragma unroll
        for (int r = 0; r < 4; r++)
            mw[r] = __ldg(mask + (size_t)row[r] * MW_ + (jA >> 5));

        // ---- stage B tile: Bs[j][f] = tf32(H[jA+j][f]) ----
#pragma unroll
        for (int q = 0; q < QT; q++) {
            int quad = tid + q * 128;
            int j  = quad / (F / 4);
            int fq = quad % (F / 4);
            float4 hv = *reinterpret_cast<const float4*>(Hh + (size_t)(jA + j) * F + 4 * fq);
            uint4 tv;
            tv.x = f2tf32(hv.x); tv.y = f2tf32(hv.y);
            tv.z = f2tf32(hv.z); tv.w = f2tf32(hv.w);
            *reinterpret_cast<uint4*>(&Bs[buf][j * SB + 4 * fq]) = tv;
        }
        // ---- stage score arrays ----
        if (tid < 96) {
            const float* src = (tid < 32) ? S2h : (tid < 64) ? Pph : Pnh;
            sSc[buf][tid] = src[jA + (tid & 31)];
        }
        __syncthreads();

        const float* s2p = sSc[buf];
        const float* ppp = sSc[buf] + 32;
        const float* npp = sSc[buf] + 64;

#pragma unroll
        for (int kk = 0; kk < 4; kk++) {
            const int c0 = kk * 8 + tg;
            const int c1 = c0 + 4;
            const float s2a = s2p[c0], s2b = s2p[c1];
            const float pa  = ppp[c0], pb  = ppp[c1];
            const float na  = npp[c0], nb  = npp[c1];
            // A fragments for 4 rows (2 m-tiles)
            u32 t0[4], t1[4];
#pragma unroll
            for (int r = 0; r < 4; r++) {
                float a0 = ((mw[r] >> c0) & 1u) ? ((s2a >= Tr[r]) ? pa * Rr[r] : na) : 0.f;
                float a1 = ((mw[r] >> c1) & 1u) ? ((s2b >= Tr[r]) ? pb * Rr[r] : nb) : 0.f;
                ds[r] += a0 + a1;
                t0[r] = f2tf32(a0);
                t1[r] = f2tf32(a1);
            }
            const u32* b0p = &Bs[buf][c0 * SB + grp];
            const u32* b1p = &Bs[buf][c1 * SB + grp];
#pragma unroll
            for (int nt = 0; nt < NT; nt++) {
                const u32 b0 = b0p[nt * 8];
                const u32 b1 = b1p[nt * 8];
                mma_tf32(acc[0][nt], t0[0], t0[1], t1[0], t1[1], b0, b1);
                mma_tf32(acc[1][nt], t0[2], t0[3], t1[2], t1[3], b0, b1);
            }
        }
    }

    // ---- denominator reduce across the 4 lanes of each row group ----
#pragma unroll
    for (int r = 0; r < 4; r++) {
        ds[r] += __shfl_xor_sync(0xffffffffu, ds[r], 1);
        ds[r] += __shfl_xor_sync(0xffffffffu, ds[r], 2);
    }

    // ---- store raw partials ----
    const size_t bidx = (size_t)(js * gridDim.y + h) * N_;
#pragma unroll
    for (int m = 0; m < 2; m++) {
        float* d0 = Pn + (bidx + row[2 * m]) * F;
        float* d1 = Pn + (bidx + row[2 * m + 1]) * F;
#pragma unroll
        for (int nt = 0; nt < NT; nt++) {
            *reinterpret_cast<float2*>(d0 + nt * 8 + 2 * tg) =
                make_float2(acc[m][nt][0], acc[m][nt][1]);
            *reinterpret_cast<float2*>(d1 + nt * 8 + 2 * tg) =
                make_float2(acc[m][nt][2], acc[m][nt][3]);
        }
    }
    if (tg == 0) {
#pragma unroll
        for (int r = 0; r < 4; r++) Pd[bidx + row[r]] = ds[r];
    }
}

// ---------------- layer-1 combine: x2 = mean_h elu(sum Pn / sum Pd) --------
__global__ void combine1_kernel(const float* __restrict__ Pn,
                                const float* __restrict__ Pd,
                                float* __restrict__ x2) {
    int idx = blockIdx.x * blockDim.x + threadIdx.x;
    int i = idx >> 6, f = idx & 63;
    float s = 0.f;
#pragma unroll
    for (int h = 0; h < NH_; h++) {
        float num = 0.f, den = 0.f;
#pragma unroll
        for (int js = 0; js < JS1_; js++) {
            size_t b = ((size_t)(js * NH_ + h)) * N_ + i;
            num += Pn[b * F1_ + f];
            den += Pd[b];
        }
        float v = num / den;
        s += (v > 0.f) ? v : (expf(v) - 1.f);
    }
    x2[idx] = 0.25f * s;
}

// ---------------- layer-2 finalize: out = elu(sum Pn / sum Pd) -------------
__global__ void finalize2_kernel(const float* __restrict__ Pn,
                                 const float* __restrict__ Pd,
                                 float* __restrict__ out) {
    int idx = blockIdx.x * blockDim.x + threadIdx.x;
    int i = idx >> 5, f = idx & 31;
    float num = 0.f, den = 0.f;
#pragma unroll
    for (int js = 0; js < JS2_; js++) {
        size_t b = (size_t)js * N_ + i;
        num += Pn[b * F2_ + f];
        den += Pd[b];
    }
    float v = num / den;
    out[idx] = (v > 0.f) ? v : (expf(v) - 1.f);
}

// ---------------------------------------------------------------------------
extern "C" void kernel_launch(void* const* d_in, const int* /*in_sizes*/, int /*n_in*/,
                              void* d_out, int /*out_size*/) {
    const float* x   = (const float*)d_in[0];
    const int*   adj = (const int*)d_in[1];
    const float* Wh  = (const float*)d_in[2];
    const float* ah  = (const float*)d_in[3];
    const float* Wo  = (const float*)d_in[4];
    const float* ao  = (const float*)d_in[5];
    float*       out = (float*)d_out;

    void* sp = nullptr;
    cudaGetSymbolAddress(&sp, g_s);
    Scratch* s = (Scratch*)sp;

    // 1) adj -> bitmask (4.7 MB, L2-resident afterwards)
    pack_kernel<<<(unsigned)((size_t)N_ * N_ / 256), 256>>>(adj, s->mask);
    // 2) layer-1 head transforms: H1[h] = x @ W_heads[h]  (RM=128 rows/block)
    gemm_kernel<F1_><<<dim3(N_ / 128, NH_), 256>>>(x, Wh, s->H1, 256);
    // 3) per-node scores & exponentials
    scores_kernel<F1_><<<(NH_ * N_) / 8, 256>>>(s->H1, ah, s->T1, s->R1, s->S21,
                                                s->E2p1, s->E2n1, NH_);
    // 4) tf32 HMMA masked attention, 4 heads, 3-way j-split -> raw partials
    attn_hmma_kernel<F1_><<<dim3(N_ / 128, NH_, JS1_), 128>>>(
        s->H1, s->T1, s->R1, s->S21, s->E2p1, s->E2n1, s->mask, s->P1n, s->P1d, JS1_);
    // 5) x2 = mean_h elu(num/den)
    combine1_kernel<<<(N_ * F1_) / 256, 256>>>(s->P1n, s->P1d, s->x2);
    // 6) layer-2 transform: H2 = x2 @ W_out  (RM=256 rows/block)
    gemm_kernel<F2_><<<dim3(N_ / 256, 1), 256>>>(s->x2, Wo, s->H2, 64);
    // 7) layer-2 scores
    scores_kernel<F2_><<<N_ / 8, 256>>>(s->H2, ao, s->T2, s->R2, s->S22,
                                        s->E2p2, s->E2n2, 1);
    // 8) layer-2 attention, 12-way j-split -> raw partials
    attn_hmma_kernel<F2_><<<dim3(N_ / 128, 1, JS2_), 128>>>(
        s->H2, s->T2, s->R2, s->S22, s->E2p2, s->E2n2, s->mask, s->P2n, s->P2d, JS2_);
    // 9) final divide + elu straight into d_out
    finalize2_kernel<<<(N_ * F2_) / 256, 256>>>(s->P2n, s->P2d, out);
}